// round 14
// baseline (speedup 1.0000x reference)
// R13 resubmit — R12 kernel unchanged; R13 bench failed on infra (container failed twice), no kernel signal.
#include <cuda_runtime.h>
#include <cuda_fp16.h>
#include <math.h>

#define N_NODES 50000
#define DIM     128
#define N_EDGES 800000
#define NEG_SLOPE 0.2f
#define CAP     96        // per-node bucket capacity; deg ~ Poisson(16), P(>=96) ~ 1e-40

// ---------------- scratch (device globals) ------------------------------------
__device__ __half g_x16[N_NODES * DIM];       // fp16 x (A operand + SAGE gather)
__device__ __half g_hp16[N_NODES * DIM];      // GAT-parent features
__device__ __half g_hc16[N_NODES * DIM];      // GAT-child features
__device__ __half g_accs16[N_NODES * DIM];    // SAGE mean (fp16, A operand for k_final)
__device__ __half g_Wp16t[DIM * DIM];         // transposed fp16 weights [n][k]
__device__ __half g_Wc16t[DIM * DIM];
__device__ __half g_Wn16t[DIM * DIM];
__device__ __half g_Wr16t[DIM * DIM];
__device__ float g_accp[N_NODES * DIM];
__device__ float g_accc[N_NODES * DIM];
__device__ float g_asp[N_NODES], g_adp[N_NODES];
__device__ float g_asc[N_NODES], g_adc[N_NODES];
__device__ int g_cnt3[3][N_NODES];            // zeroed at load; consumed+re-zeroed by k_agg
__device__ int g_bktP[N_NODES * CAP];         // per-dst src buckets
__device__ int g_bktC[N_NODES * CAP];
__device__ int g_bktS[N_NODES * CAP];

// ---------------- helpers -----------------------------------------------------
__device__ __forceinline__ float lrelu(float v) { return v > 0.f ? v : NEG_SLOPE * v; }

__device__ __forceinline__ float4 h2f4(uint2 v) {
    __half2 a = *reinterpret_cast<__half2*>(&v.x);
    __half2 b = *reinterpret_cast<__half2*>(&v.y);
    float2 fa = __half22float2(a), fb = __half22float2(b);
    return make_float4(fa.x, fa.y, fb.x, fb.y);
}

__device__ __forceinline__ void mma16816(float* c, const unsigned* a, unsigned b0, unsigned b1) {
    asm volatile(
        "mma.sync.aligned.m16n8k16.row.col.f32.f16.f16.f32 "
        "{%0,%1,%2,%3}, {%4,%5,%6,%7}, {%8,%9}, {%0,%1,%2,%3};"
        : "+f"(c[0]), "+f"(c[1]), "+f"(c[2]), "+f"(c[3])
        : "r"(a[0]), "r"(a[1]), "r"(a[2]), "r"(a[3]), "r"(b0), "r"(b1));
}

// ---------------- prep: fp16 conversions --------------------------------------
__global__ void __launch_bounds__(256) k_prepx(const float* __restrict__ x) {
    int i = blockIdx.x * 256 + threadIdx.x;        // half2 index; 3.2M total
    ((__half2*)g_x16)[i] = __floats2half2_rn(x[2 * i], x[2 * i + 1]);
}

__global__ void __launch_bounds__(256) k_prepw(
    const float* __restrict__ Wp, const float* __restrict__ Wc,
    const float* __restrict__ Wn, const float* __restrict__ Wr)
{
    int m = blockIdx.y;
    const float* W = (m == 0) ? Wp : (m == 1) ? Wc : (m == 2) ? Wn : Wr;
    __half* Wt = (m == 0) ? g_Wp16t : (m == 1) ? g_Wc16t : (m == 2) ? g_Wn16t : g_Wr16t;
    int idx = blockIdx.x * 256 + threadIdx.x;      // 16384 per matrix
    int k = idx >> 7, n = idx & 127;
    Wt[n * DIM + k] = __float2half_rn(W[idx]);
}

// ---------------- single-pass bucket CSR build --------------------------------
__global__ void __launch_bounds__(256) k_fillb(
    const int* __restrict__ sP, const int* __restrict__ dP,
    const int* __restrict__ sC, const int* __restrict__ dC,
    const int* __restrict__ sS, const int* __restrict__ dS)
{
    int g = blockIdx.y;
    int e = blockIdx.x * 256 + threadIdx.x;
    const int* src = (g == 0) ? sP : (g == 1) ? sC : sS;
    const int* dst = (g == 0) ? dP : (g == 1) ? dC : dS;
    int* bkt       = (g == 0) ? g_bktP : (g == 1) ? g_bktC : g_bktS;
    int s = src[e], d = dst[e];
    int pos = atomicAdd(&g_cnt3[g][d], 1);
    if (pos < CAP) bkt[d * CAP + pos] = s;   // clamp guards OOB; overflow would surface as rel_err
}

// ---------------- K_feat: h = x·W via HMMA; alpha dots from fp32 acc ----------
// 8 warps/block: warps 0-3 -> Wp, warps 4-7 -> Wc, same 64 rows.
__global__ void __launch_bounds__(256) k_feat(
    const float* __restrict__ apS, const float* __restrict__ apD,
    const float* __restrict__ acS, const float* __restrict__ acD)
{
    const int w = threadIdx.x >> 5, lane = threadIdx.x & 31;
    const int mat = w >> 2;
    const int rA  = blockIdx.x * 64 + (w & 3) * 16 + (lane >> 2);
    const int rA0 = min(rA, N_NODES - 1);
    const int rA1 = min(rA + 8, N_NODES - 1);
    const int kc  = (lane & 3) * 2;
    const __half* Wt = mat ? g_Wc16t : g_Wp16t;
    __half* hout     = mat ? g_hc16  : g_hp16;

    float acc[16][4];
#pragma unroll
    for (int nt = 0; nt < 16; nt++) { acc[nt][0] = acc[nt][1] = acc[nt][2] = acc[nt][3] = 0.f; }

#pragma unroll 2
    for (int ks = 0; ks < 8; ks++) {
        const int k0 = ks * 16;
        unsigned a[4];
        a[0] = *(const unsigned*)(g_x16 + (size_t)rA0 * DIM + k0 + kc);
        a[1] = *(const unsigned*)(g_x16 + (size_t)rA1 * DIM + k0 + kc);
        a[2] = *(const unsigned*)(g_x16 + (size_t)rA0 * DIM + k0 + kc + 8);
        a[3] = *(const unsigned*)(g_x16 + (size_t)rA1 * DIM + k0 + kc + 8);
#pragma unroll
        for (int nt = 0; nt < 16; nt++) {
            const int n = nt * 8 + (lane >> 2);
            unsigned b0 = *(const unsigned*)(Wt + (size_t)n * DIM + k0 + kc);
            unsigned b1 = *(const unsigned*)(Wt + (size_t)n * DIM + k0 + kc + 8);
            mma16816(acc[nt], a, b0, b1);
        }
    }

    // epilogue: store fp16 h rows + fp32 alpha dot products
    const float* aS = mat ? acS : apS;
    const float* aD = mat ? acD : apD;
    float dS0 = 0.f, dD0 = 0.f, dS1 = 0.f, dD1 = 0.f;
    const bool ok0 = rA < N_NODES, ok1 = (rA + 8) < N_NODES;
#pragma unroll
    for (int nt = 0; nt < 16; nt++) {
        const int c0 = nt * 8 + (lane & 3) * 2;
        float s0 = aS[c0], s1 = aS[c0 + 1], d0 = aD[c0], d1 = aD[c0 + 1];
        dS0 += acc[nt][0] * s0 + acc[nt][1] * s1;
        dD0 += acc[nt][0] * d0 + acc[nt][1] * d1;
        dS1 += acc[nt][2] * s0 + acc[nt][3] * s1;
        dD1 += acc[nt][2] * d0 + acc[nt][3] * d1;
        if (ok0) *(__half2*)(hout + (size_t)rA * DIM + c0)       = __floats2half2_rn(acc[nt][0], acc[nt][1]);
        if (ok1) *(__half2*)(hout + (size_t)(rA + 8) * DIM + c0) = __floats2half2_rn(acc[nt][2], acc[nt][3]);
    }
    // reduce over the 4 lanes sharing each row (lane groups of 4)
    dS0 += __shfl_xor_sync(0xffffffffu, dS0, 1); dS0 += __shfl_xor_sync(0xffffffffu, dS0, 2);
    dD0 += __shfl_xor_sync(0xffffffffu, dD0, 1); dD0 += __shfl_xor_sync(0xffffffffu, dD0, 2);
    dS1 += __shfl_xor_sync(0xffffffffu, dS1, 1); dS1 += __shfl_xor_sync(0xffffffffu, dS1, 2);
    dD1 += __shfl_xor_sync(0xffffffffu, dD1, 1); dD1 += __shfl_xor_sync(0xffffffffu, dD1, 2);
    if ((lane & 3) == 0) {
        float* asO = mat ? g_asc : g_asp;
        float* adO = mat ? g_adc : g_adp;
        if (ok0) { asO[rA] = dS0;     adO[rA] = dD0; }
        if (ok1) { asO[rA + 8] = dS1; adO[rA + 8] = dD1; }
    }
}

// ---------------- K_agg: chunked warp-cooperative fp16 gather ------------------
// blockIdx.y: 0 = GAT parent, 1 = GAT child, 2 = SAGE(mean of x)
// Maxless softmax: exp(e)/sum(exp(e)); |e| small, fp32 safe.
__global__ void __launch_bounds__(256) k_agg()
{
    const int which = blockIdx.y;
    const int node  = (blockIdx.x * 256 + threadIdx.x) >> 5;   // 6250*8 = 50000 exact
    const int lane  = threadIdx.x & 31;

    const int* bkt = (which == 0) ? g_bktP : (which == 1) ? g_bktC : g_bktS;
    const __half* h16 = (which == 0) ? g_hp16 : (which == 1) ? g_hc16 : g_x16;

    // consume degree, then restore the zero invariant for graph replays
    int* cntp = &g_cnt3[which][node];
    const int deg = *cntp;                    // broadcast load (all lanes, same addr)
    if (lane == 0) *cntp = 0;
    const int base = node * CAP;
    const int end  = base + deg;
    float4 a;

    if (which < 2) {
        const float* as_ = which ? g_asc : g_asp;
        const float* ad_ = which ? g_adc : g_adp;
        const float ad_i = ad_[node];

        float den = __expf(lrelu(as_[node] + ad_i));   // self loop
        uint2 hvs = ((const uint2*)(h16 + (size_t)node * DIM))[lane];
        float4 fs = h2f4(hvs);
        a.x = den * fs.x; a.y = den * fs.y; a.z = den * fs.z; a.w = den * fs.w;

        for (int cs = base; cs < end; cs += 32) {
            int idx = cs + lane;
            bool vld = idx < end;
            int   s  = vld ? bkt[idx] : 0;
            float ex = vld ? __expf(lrelu(as_[s] + ad_i)) : 0.f;
            float exs = ex;
#pragma unroll
            for (int o = 16; o; o >>= 1)
                exs += __shfl_xor_sync(0xffffffffu, exs, o);
            den += exs;
            const int n = min(32, end - cs);
#pragma unroll 8
            for (int t = 0; t < n; t++) {
                int   sb  = __shfl_sync(0xffffffffu, s,  t);
                float exb = __shfl_sync(0xffffffffu, ex, t);
                uint2 hv = ((const uint2*)(h16 + (size_t)sb * DIM))[lane];
                float4 f = h2f4(hv);
                a.x = fmaf(exb, f.x, a.x); a.y = fmaf(exb, f.y, a.y);
                a.z = fmaf(exb, f.z, a.z); a.w = fmaf(exb, f.w, a.w);
            }
        }
        float r = 1.f / den;
        a.x *= r; a.y *= r; a.z *= r; a.w *= r;
        float* acc = which ? g_accc : g_accp;
        ((float4*)(acc + (size_t)node * DIM))[lane] = a;
    } else {
        a = make_float4(0.f, 0.f, 0.f, 0.f);
        for (int cs = base; cs < end; cs += 32) {
            int idx = cs + lane;
            int s   = (idx < end) ? bkt[idx] : 0;
            const int n = min(32, end - cs);
#pragma unroll 8
            for (int t = 0; t < n; t++) {
                int sb = __shfl_sync(0xffffffffu, s, t);
                uint2 xv = ((const uint2*)(h16 + (size_t)sb * DIM))[lane];
                float4 f = h2f4(xv);
                a.x += f.x; a.y += f.y; a.z += f.z; a.w += f.w;
            }
        }
        float r = 1.f / fmaxf((float)deg, 1.f);
        // fp16 mean for k_final's A operand
        uint2 pk;
        *reinterpret_cast<__half2*>(&pk.x) = __floats2half2_rn(a.x * r, a.y * r);
        *reinterpret_cast<__half2*>(&pk.y) = __floats2half2_rn(a.z * r, a.w * r);
        ((uint2*)(g_accs16 + (size_t)node * DIM))[lane] = pk;
    }
}

// ---------------- K_final: mean·Wn + x·Wr via HMMA + combine ------------------
// 4 warps/block, 16 rows each.
__global__ void __launch_bounds__(128) k_final(
    const float* __restrict__ bp, const float* __restrict__ bc,
    const float* __restrict__ bs, float* __restrict__ out)
{
    const int w = threadIdx.x >> 5, lane = threadIdx.x & 31;
    const int rA  = blockIdx.x * 64 + w * 16 + (lane >> 2);
    const int rA0 = min(rA, N_NODES - 1);
    const int rA1 = min(rA + 8, N_NODES - 1);
    const int kc  = (lane & 3) * 2;

    float acc[16][4];
#pragma unroll
    for (int nt = 0; nt < 16; nt++) { acc[nt][0] = acc[nt][1] = acc[nt][2] = acc[nt][3] = 0.f; }

    // chain 1: mean(accs16) · Wn
#pragma unroll 2
    for (int ks = 0; ks < 8; ks++) {
        const int k0 = ks * 16;
        unsigned a[4];
        a[0] = *(const unsigned*)(g_accs16 + (size_t)rA0 * DIM + k0 + kc);
        a[1] = *(const unsigned*)(g_accs16 + (size_t)rA1 * DIM + k0 + kc);
        a[2] = *(const unsigned*)(g_accs16 + (size_t)rA0 * DIM + k0 + kc + 8);
        a[3] = *(const unsigned*)(g_accs16 + (size_t)rA1 * DIM + k0 + kc + 8);
#pragma unroll
        for (int nt = 0; nt < 16; nt++) {
            const int n = nt * 8 + (lane >> 2);
            unsigned b0 = *(const unsigned*)(g_Wn16t + (size_t)n * DIM + k0 + kc);
            unsigned b1 = *(const unsigned*)(g_Wn16t + (size_t)n * DIM + k0 + kc + 8);
            mma16816(acc[nt], a, b0, b1);
        }
    }
    // chain 2: x · Wr (same accumulators)
#pragma unroll 2
    for (int ks = 0; ks < 8; ks++) {
        const int k0 = ks * 16;
        unsigned a[4];
        a[0] = *(const unsigned*)(g_x16 + (size_t)rA0 * DIM + k0 + kc);
        a[1] = *(const unsigned*)(g_x16 + (size_t)rA1 * DIM + k0 + kc);
        a[2] = *(const unsigned*)(g_x16 + (size_t)rA0 * DIM + k0 + kc + 8);
        a[3] = *(const unsigned*)(g_x16 + (size_t)rA1 * DIM + k0 + kc + 8);
#pragma unroll
        for (int nt = 0; nt < 16; nt++) {
            const int n = nt * 8 + (lane >> 2);
            unsigned b0 = *(const unsigned*)(g_Wr16t + (size_t)n * DIM + k0 + kc);
            unsigned b1 = *(const unsigned*)(g_Wr16t + (size_t)n * DIM + k0 + kc + 8);
            mma16816(acc[nt], a, b0, b1);
        }
    }

    const bool ok0 = rA < N_NODES, ok1 = (rA + 8) < N_NODES;
#pragma unroll
    for (int nt = 0; nt < 16; nt++) {
        const int c0 = nt * 8 + (lane & 3) * 2;
        float b0 = bp[c0] + bc[c0] + bs[c0];
        float b1 = bp[c0 + 1] + bc[c0 + 1] + bs[c0 + 1];
        if (ok0) {
            float2 p = *(const float2*)(g_accp + (size_t)rA * DIM + c0);
            float2 c = *(const float2*)(g_accc + (size_t)rA * DIM + c0);
            float2 o;
            o.x = (acc[nt][0] + p.x + c.x + b0) * (1.f / 3.f);
            o.y = (acc[nt][1] + p.y + c.y + b1) * (1.f / 3.f);
            *(float2*)(out + (size_t)rA * DIM + c0) = o;
        }
        if (ok1) {
            float2 p = *(const float2*)(g_accp + (size_t)(rA + 8) * DIM + c0);
            float2 c = *(const float2*)(g_accc + (size_t)(rA + 8) * DIM + c0);
            float2 o;
            o.x = (acc[nt][2] + p.x + c.x + b0) * (1.f / 3.f);
            o.y = (acc[nt][3] + p.y + c.y + b1) * (1.f / 3.f);
            *(float2*)(out + (size_t)(rA + 8) * DIM + c0) = o;
        }
    }
}

// ---------------- launch ------------------------------------------------------
extern "C" void kernel_launch(void* const* d_in, const int* in_sizes, int n_in,
                              void* d_out, int out_size)
{
    const float* x    = (const float*)d_in[0];
    const int*   eip  = (const int*)d_in[1];   // [2, E]: src then dst
    const int*   eic  = (const int*)d_in[2];
    const int*   eir  = (const int*)d_in[3];
    const float* gpW  = (const float*)d_in[4];
    const float* gpaS = (const float*)d_in[5];
    const float* gpaD = (const float*)d_in[6];
    const float* gpB  = (const float*)d_in[7];
    const float* gcW  = (const float*)d_in[8];
    const float* gcaS = (const float*)d_in[9];
    const float* gcaD = (const float*)d_in[10];
    const float* gcB  = (const float*)d_in[11];
    const float* sgWn = (const float*)d_in[12];
    const float* sgWr = (const float*)d_in[13];
    const float* sgB  = (const float*)d_in[14];
    float* out = (float*)d_out;

    // fp16 prep
    k_prepx<<<(N_NODES * DIM / 2) / 256, 256>>>(x);
    k_prepw<<<dim3(64, 4), 256>>>(gpW, gcW, sgWn, sgWr);
    // single-pass bucket CSR build (counts start zeroed; k_agg restores them)
    k_fillb<<<dim3(N_EDGES / 256, 3), 256>>>(eip, eip + N_EDGES,
                                             eic, eic + N_EDGES,
                                             eir, eir + N_EDGES);
    // tensor-core feature GEMMs + alpha scalars (launch #4 — ncu slot)
    k_feat<<<782, 256>>>(gpaS, gpaD, gcaS, gcaD);
    // per-dst aggregation (2 GATs + SAGE mean)
    k_agg<<<dim3(N_NODES / 8, 3), 256>>>();
    // tensor-core SAGE GEMMs + combine
    k_final<<<782, 128>>>(gpB, gcB, sgB, out);
}

// round 15
// speedup vs baseline: 1.9371x; 1.9371x over previous
// R14: revert CSR to measured-330 count/alloc/fill; k_feat/k_final B-fragments from padded smem (kills 8-line LDG pattern).
#include <cuda_runtime.h>
#include <cuda_fp16.h>
#include <math.h>

#define N_NODES 50000
#define DIM     128
#define N_EDGES 800000
#define NEG_SLOPE 0.2f
#define WSTRIDE 68        // padded W row stride in 32-bit words: bank = 4n+kc, conflict-free

// ---------------- scratch (device globals) ------------------------------------
__device__ __half g_x16[N_NODES * DIM];
__device__ __half g_hp16[N_NODES * DIM];
__device__ __half g_hc16[N_NODES * DIM];
__device__ __half g_accs16[N_NODES * DIM];
__device__ __half g_Wp16t[DIM * DIM];         // transposed fp16 weights [n][k]
__device__ __half g_Wc16t[DIM * DIM];
__device__ __half g_Wn16t[DIM * DIM];
__device__ __half g_Wr16t[DIM * DIM];
__device__ float g_accp[N_NODES * DIM];
__device__ float g_accc[N_NODES * DIM];
__device__ float g_asp[N_NODES], g_adp[N_NODES];
__device__ float g_asc[N_NODES], g_adc[N_NODES];
__device__ int g_cnt3[3][N_NODES];            // zeroed at load; re-zeroed by k_alloc each run
__device__ int g_rp3[3][N_NODES];             // segment start (not monotone across nodes)
__device__ int g_rpe3[3][N_NODES];            // segment end
__device__ int g_cur3[3][N_NODES];
__device__ int g_base3[3];                    // bump allocators; reset by k_count
__device__ int g_csrP[N_EDGES], g_csrC[N_EDGES], g_csrS[N_EDGES];

// ---------------- helpers -----------------------------------------------------
__device__ __forceinline__ float lrelu(float v) { return v > 0.f ? v : NEG_SLOPE * v; }

__device__ __forceinline__ float4 h2f4(uint2 v) {
    __half2 a = *reinterpret_cast<__half2*>(&v.x);
    __half2 b = *reinterpret_cast<__half2*>(&v.y);
    float2 fa = __half22float2(a), fb = __half22float2(b);
    return make_float4(fa.x, fa.y, fb.x, fb.y);
}

__device__ __forceinline__ void mma16816(float* c, const unsigned* a, unsigned b0, unsigned b1) {
    asm volatile(
        "mma.sync.aligned.m16n8k16.row.col.f32.f16.f16.f32 "
        "{%0,%1,%2,%3}, {%4,%5,%6,%7}, {%8,%9}, {%0,%1,%2,%3};"
        : "+f"(c[0]), "+f"(c[1]), "+f"(c[2]), "+f"(c[3])
        : "r"(a[0]), "r"(a[1]), "r"(a[2]), "r"(a[3]), "r"(b0), "r"(b1));
}

// ---------------- prep: fp16 conversions --------------------------------------
__global__ void __launch_bounds__(256) k_prepx(const float* __restrict__ x) {
    int i = blockIdx.x * 256 + threadIdx.x;
    ((__half2*)g_x16)[i] = __floats2half2_rn(x[2 * i], x[2 * i + 1]);
}

__global__ void __launch_bounds__(256) k_prepw(
    const float* __restrict__ Wp, const float* __restrict__ Wc,
    const float* __restrict__ Wn, const float* __restrict__ Wr)
{
    int m = blockIdx.y;
    const float* W = (m == 0) ? Wp : (m == 1) ? Wc : (m == 2) ? Wn : Wr;
    __half* Wt = (m == 0) ? g_Wp16t : (m == 1) ? g_Wc16t : (m == 2) ? g_Wn16t : g_Wr16t;
    int idx = blockIdx.x * 256 + threadIdx.x;
    int k = idx >> 7, n = idx & 127;
    Wt[n * DIM + k] = __float2half_rn(W[idx]);
}

// ---------------- CSR build (count -> atomic segment alloc -> fill) ------------
__global__ void __launch_bounds__(256) k_count(
    const int* __restrict__ dP, const int* __restrict__ dC, const int* __restrict__ dS)
{
    int g = blockIdx.y;
    if (blockIdx.x == 0 && threadIdx.x == 0) g_base3[g] = 0;
    int e = blockIdx.x * 256 + threadIdx.x;
    const int* d = (g == 0) ? dP : (g == 1) ? dC : dS;
    atomicAdd(&g_cnt3[g][d[e]], 1);
}

__global__ void __launch_bounds__(256) k_alloc() {
    int g = blockIdx.y;
    int i = blockIdx.x * 256 + threadIdx.x;        // 196*256 = 50176 >= 50000
    int lane = threadIdx.x & 31;
    int deg = (i < N_NODES) ? g_cnt3[g][i] : 0;
    int s = deg;
#pragma unroll
    for (int o = 1; o < 32; o <<= 1) {
        int u = __shfl_up_sync(0xffffffffu, s, o);
        if (lane >= o) s += u;
    }
    int total = __shfl_sync(0xffffffffu, s, 31);
    int base0 = 0;
    if (lane == 0) base0 = atomicAdd(&g_base3[g], total);
    base0 = __shfl_sync(0xffffffffu, base0, 0);
    int mybase = base0 + s - deg;
    if (i < N_NODES) {
        g_rp3[g][i]  = mybase;
        g_rpe3[g][i] = mybase + deg;
        g_cur3[g][i] = mybase;
        g_cnt3[g][i] = 0;                          // restore invariant for graph replays
    }
}

__global__ void __launch_bounds__(256) k_fill(
    const int* __restrict__ sP, const int* __restrict__ dP,
    const int* __restrict__ sC, const int* __restrict__ dC,
    const int* __restrict__ sS, const int* __restrict__ dS)
{
    int g = blockIdx.y;
    int e = blockIdx.x * 256 + threadIdx.x;
    const int* src = (g == 0) ? sP : (g == 1) ? sC : sS;
    const int* dst = (g == 0) ? dP : (g == 1) ? dC : dS;
    int* csr       = (g == 0) ? g_csrP : (g == 1) ? g_csrC : g_csrS;
    int pos = atomicAdd(&g_cur3[g][dst[e]], 1);
    csr[pos] = src[e];
}

// ---------------- K_feat: h = x·W via HMMA, W staged in padded smem -----------
// grid (782, 2): blockIdx.y = matrix (0=Wp, 1=Wc); 4 warps, 16 rows each.
__global__ void __launch_bounds__(128) k_feat(
    const float* __restrict__ apS, const float* __restrict__ apD,
    const float* __restrict__ acS, const float* __restrict__ acD)
{
    __shared__ unsigned sW[DIM * WSTRIDE];   // 34816 B
    const int mat = blockIdx.y;
    const __half* Wt = mat ? g_Wc16t : g_Wp16t;

    // stage W: 128 rows x 64 words, padded to WSTRIDE words per row
    for (int i = threadIdx.x; i < DIM * 16; i += 128) {
        int row = i >> 4, c = i & 15;
        uint4 v = ((const uint4*)(Wt + row * DIM))[c];
        *(uint4*)&sW[row * WSTRIDE + c * 4] = v;
    }
    __syncthreads();

    const int w = threadIdx.x >> 5, lane = threadIdx.x & 31;
    const int rA  = blockIdx.x * 64 + w * 16 + (lane >> 2);
    const int rA0 = min(rA, N_NODES - 1);
    const int rA1 = min(rA + 8, N_NODES - 1);
    const int kc  = (lane & 3) * 2;
    const int bq  = lane & 3;                // word offset within k-half
    __half* hout  = mat ? g_hc16 : g_hp16;

    float acc[16][4];
#pragma unroll
    for (int nt = 0; nt < 16; nt++) { acc[nt][0] = acc[nt][1] = acc[nt][2] = acc[nt][3] = 0.f; }

#pragma unroll 2
    for (int ks = 0; ks < 8; ks++) {
        const int k0 = ks * 16;
        unsigned a[4];
        a[0] = *(const unsigned*)(g_x16 + (size_t)rA0 * DIM + k0 + kc);
        a[1] = *(const unsigned*)(g_x16 + (size_t)rA1 * DIM + k0 + kc);
        a[2] = *(const unsigned*)(g_x16 + (size_t)rA0 * DIM + k0 + kc + 8);
        a[3] = *(const unsigned*)(g_x16 + (size_t)rA1 * DIM + k0 + kc + 8);
        const int kw = ks * 8 + bq;
#pragma unroll
        for (int nt = 0; nt < 16; nt++) {
            const unsigned* wrow = &sW[(nt * 8 + (lane >> 2)) * WSTRIDE + kw];
            mma16816(acc[nt], a, wrow[0], wrow[4]);
        }
    }

    // epilogue: store fp16 h rows + fp32 alpha dot products
    const float* aS = mat ? acS : apS;
    const float* aD = mat ? acD : apD;
    float dS0 = 0.f, dD0 = 0.f, dS1 = 0.f, dD1 = 0.f;
    const bool ok0 = rA < N_NODES, ok1 = (rA + 8) < N_NODES;
#pragma unroll
    for (int nt = 0; nt < 16; nt++) {
        const int c0 = nt * 8 + (lane & 3) * 2;
        float s0 = aS[c0], s1 = aS[c0 + 1], d0 = aD[c0], d1 = aD[c0 + 1];
        dS0 += acc[nt][0] * s0 + acc[nt][1] * s1;
        dD0 += acc[nt][0] * d0 + acc[nt][1] * d1;
        dS1 += acc[nt][2] * s0 + acc[nt][3] * s1;
        dD1 += acc[nt][2] * d0 + acc[nt][3] * d1;
        if (ok0) *(__half2*)(hout + (size_t)rA * DIM + c0)       = __floats2half2_rn(acc[nt][0], acc[nt][1]);
        if (ok1) *(__half2*)(hout + (size_t)(rA + 8) * DIM + c0) = __floats2half2_rn(acc[nt][2], acc[nt][3]);
    }
    dS0 += __shfl_xor_sync(0xffffffffu, dS0, 1); dS0 += __shfl_xor_sync(0xffffffffu, dS0, 2);
    dD0 += __shfl_xor_sync(0xffffffffu, dD0, 1); dD0 += __shfl_xor_sync(0xffffffffu, dD0, 2);
    dS1 += __shfl_xor_sync(0xffffffffu, dS1, 1); dS1 += __shfl_xor_sync(0xffffffffu, dS1, 2);
    dD1 += __shfl_xor_sync(0xffffffffu, dD1, 1); dD1 += __shfl_xor_sync(0xffffffffu, dD1, 2);
    if ((lane & 3) == 0) {
        float* asO = mat ? g_asc : g_asp;
        float* adO = mat ? g_adc : g_adp;
        if (ok0) { asO[rA] = dS0;     adO[rA] = dD0; }
        if (ok1) { asO[rA + 8] = dS1; adO[rA + 8] = dD1; }
    }
}

// ---------------- K_agg: chunked warp-cooperative fp16 gather (R11 design) -----
__global__ void __launch_bounds__(256) k_agg()
{
    const int which = blockIdx.y;
    const int node  = (blockIdx.x * 256 + threadIdx.x) >> 5;   // 6250*8 = 50000 exact
    const int lane  = threadIdx.x & 31;

    const int* csr = (which == 0) ? g_csrP : (which == 1) ? g_csrC : g_csrS;
    const __half* h16 = (which == 0) ? g_hp16 : (which == 1) ? g_hc16 : g_x16;

    const int base = g_rp3[which][node], end = g_rpe3[which][node];
    float4 a;

    if (which < 2) {
        const float* as_ = which ? g_asc : g_asp;
        const float* ad_ = which ? g_adc : g_adp;
        const float ad_i = ad_[node];

        float den = __expf(lrelu(as_[node] + ad_i));   // self loop
        uint2 hvs = ((const uint2*)(h16 + (size_t)node * DIM))[lane];
        float4 fs = h2f4(hvs);
        a.x = den * fs.x; a.y = den * fs.y; a.z = den * fs.z; a.w = den * fs.w;

        for (int cs = base; cs < end; cs += 32) {
            int idx = cs + lane;
            bool vld = idx < end;
            int   s  = vld ? csr[idx] : 0;
            float ex = vld ? __expf(lrelu(as_[s] + ad_i)) : 0.f;
            float exs = ex;
#pragma unroll
            for (int o = 16; o; o >>= 1)
                exs += __shfl_xor_sync(0xffffffffu, exs, o);
            den += exs;
            const int n = min(32, end - cs);
#pragma unroll 8
            for (int t = 0; t < n; t++) {
                int   sb  = __shfl_sync(0xffffffffu, s,  t);
                float exb = __shfl_sync(0xffffffffu, ex, t);
                uint2 hv = ((const uint2*)(h16 + (size_t)sb * DIM))[lane];
                float4 f = h2f4(hv);
                a.x = fmaf(exb, f.x, a.x); a.y = fmaf(exb, f.y, a.y);
                a.z = fmaf(exb, f.z, a.z); a.w = fmaf(exb, f.w, a.w);
            }
        }
        float r = 1.f / den;
        a.x *= r; a.y *= r; a.z *= r; a.w *= r;
        float* acc = which ? g_accc : g_accp;
        ((float4*)(acc + (size_t)node * DIM))[lane] = a;
    } else {
        a = make_float4(0.f, 0.f, 0.f, 0.f);
        for (int cs = base; cs < end; cs += 32) {
            int idx = cs + lane;
            int s   = (idx < end) ? csr[idx] : 0;
            const int n = min(32, end - cs);
#pragma unroll 8
            for (int t = 0; t < n; t++) {
                int sb = __shfl_sync(0xffffffffu, s, t);
                uint2 xv = ((const uint2*)(h16 + (size_t)sb * DIM))[lane];
                float4 f = h2f4(xv);
                a.x += f.x; a.y += f.y; a.z += f.z; a.w += f.w;
            }
        }
        float r = 1.f / fmaxf((float)(end - base), 1.f);
        uint2 pk;
        *reinterpret_cast<__half2*>(&pk.x) = __floats2half2_rn(a.x * r, a.y * r);
        *reinterpret_cast<__half2*>(&pk.y) = __floats2half2_rn(a.z * r, a.w * r);
        ((uint2*)(g_accs16 + (size_t)node * DIM))[lane] = pk;
    }
}

// ---------------- K_final: mean·Wn + x·Wr via HMMA, W staged in smem ----------
// 4 warps/block, 16 rows each; Wn then Wr staged sequentially in one buffer.
__global__ void __launch_bounds__(128) k_final(
    const float* __restrict__ bp, const float* __restrict__ bc,
    const float* __restrict__ bs, float* __restrict__ out)
{
    __shared__ unsigned sW[DIM * WSTRIDE];   // 34816 B, reused for Wn then Wr
    const int w = threadIdx.x >> 5, lane = threadIdx.x & 31;
    const int rA  = blockIdx.x * 64 + w * 16 + (lane >> 2);
    const int rA0 = min(rA, N_NODES - 1);
    const int rA1 = min(rA + 8, N_NODES - 1);
    const int kc  = (lane & 3) * 2;
    const int bq  = lane & 3;

    float acc[16][4];
#pragma unroll
    for (int nt = 0; nt < 16; nt++) { acc[nt][0] = acc[nt][1] = acc[nt][2] = acc[nt][3] = 0.f; }

    // ---- chain 1: mean(accs16) · Wn ----
    for (int i = threadIdx.x; i < DIM * 16; i += 128) {
        int row = i >> 4, c = i & 15;
        uint4 v = ((const uint4*)(g_Wn16t + row * DIM))[c];
        *(uint4*)&sW[row * WSTRIDE + c * 4] = v;
    }
    __syncthreads();
#pragma unroll 2
    for (int ks = 0; ks < 8; ks++) {
        const int k0 = ks * 16;
        unsigned a[4];
        a[0] = *(const unsigned*)(g_accs16 + (size_t)rA0 * DIM + k0 + kc);
        a[1] = *(const unsigned*)(g_accs16 + (size_t)rA1 * DIM + k0 + kc);
        a[2] = *(const unsigned*)(g_accs16 + (size_t)rA0 * DIM + k0 + kc + 8);
        a[3] = *(const unsigned*)(g_accs16 + (size_t)rA1 * DIM + k0 + kc + 8);
        const int kw = ks * 8 + bq;
#pragma unroll
        for (int nt = 0; nt < 16; nt++) {
            const unsigned* wrow = &sW[(nt * 8 + (lane >> 2)) * WSTRIDE + kw];
            mma16816(acc[nt], a, wrow[0], wrow[4]);
        }
    }
    __syncthreads();   // drain before restaging

    // ---- chain 2: x · Wr ----
    for (int i = threadIdx.x; i < DIM * 16; i += 128) {
        int row = i >> 4, c = i & 15;
        uint4 v = ((const uint4*)(g_Wr16t + row * DIM))[c];
        *(uint4*)&sW[row * WSTRIDE + c * 4] = v;
    }
    __syncthreads();
#pragma unroll 2
    for (int ks = 0; ks < 8; ks++) {
        const int k0 = ks * 16;
        unsigned a[4];
        a[0] = *(const unsigned*)(g_x16 + (size_t)rA0 * DIM + k0 + kc);
        a[1] = *(const unsigned*)(g_x16 + (size_t)rA1 * DIM + k0 + kc);
        a[2] = *(const unsigned*)(g_x16 + (size_t)rA0 * DIM + k0 + kc + 8);
        a[3] = *(const unsigned*)(g_x16 + (size_t)rA1 * DIM + k0 + kc + 8);
        const int kw = ks * 8 + bq;
#pragma unroll
        for (int nt = 0; nt < 16; nt++) {
            const unsigned* wrow = &sW[(nt * 8 + (lane >> 2)) * WSTRIDE + kw];
            mma16816(acc[nt], a, wrow[0], wrow[4]);
        }
    }

    const bool ok0 = rA < N_NODES, ok1 = (rA + 8) < N_NODES;
#pragma unroll
    for (int nt = 0; nt < 16; nt++) {
        const int c0 = nt * 8 + (lane & 3) * 2;
        float b0 = bp[c0] + bc[c0] + bs[c0];
        float b1 = bp[c0 + 1] + bc[c0 + 1] + bs[c0 + 1];
        if (ok0) {
            float2 p = *(const float2*)(g_accp + (size_t)rA * DIM + c0);
            float2 c = *(const float2*)(g_accc + (size_t)rA * DIM + c0);
            float2 o;
            o.x = (acc[nt][0] + p.x + c.x + b0) * (1.f / 3.f);
            o.y = (acc[nt][1] + p.y + c.y + b1) * (1.f / 3.f);
            *(float2*)(out + (size_t)rA * DIM + c0) = o;
        }
        if (ok1) {
            float2 p = *(const float2*)(g_accp + (size_t)(rA + 8) * DIM + c0);
            float2 c = *(const float2*)(g_accc + (size_t)(rA + 8) * DIM + c0);
            float2 o;
            o.x = (acc[nt][2] + p.x + c.x + b0) * (1.f / 3.f);
            o.y = (acc[nt][3] + p.y + c.y + b1) * (1.f / 3.f);
            *(float2*)(out + (size_t)(rA + 8) * DIM + c0) = o;
        }
    }
}

// ---------------- launch ------------------------------------------------------
extern "C" void kernel_launch(void* const* d_in, const int* in_sizes, int n_in,
                              void* d_out, int out_size)
{
    const float* x    = (const float*)d_in[0];
    const int*   eip  = (const int*)d_in[1];   // [2, E]: src then dst
    const int*   eic  = (const int*)d_in[2];
    const int*   eir  = (const int*)d_in[3];
    const float* gpW  = (const float*)d_in[4];
    const float* gpaS = (const float*)d_in[5];
    const float* gpaD = (const float*)d_in[6];
    const float* gpB  = (const float*)d_in[7];
    const float* gcW  = (const float*)d_in[8];
    const float* gcaS = (const float*)d_in[9];
    const float* gcaD = (const float*)d_in[10];
    const float* gcB  = (const float*)d_in[11];
    const float* sgWn = (const float*)d_in[12];
    const float* sgWr = (const float*)d_in[13];
    const float* sgB  = (const float*)d_in[14];
    float* out = (float*)d_out;

    // fp16 prep
    k_prepx<<<(N_NODES * DIM / 2) / 256, 256>>>(x);
    k_prepw<<<dim3(64, 4), 256>>>(gpW, gcW, sgWn, sgWr);
    // CSR build: count -> atomic segment alloc -> fill
    k_count<<<dim3(N_EDGES / 256, 3), 256>>>(eip + N_EDGES, eic + N_EDGES, eir + N_EDGES);
    k_alloc<<<dim3(196, 3), 256>>>();
    k_fill<<<dim3(N_EDGES / 256, 3), 256>>>(eip, eip + N_EDGES,
                                            eic, eic + N_EDGES,
                                            eir, eir + N_EDGES);
    // tensor-core feature GEMMs (W staged in smem) + alpha scalars
    k_feat<<<dim3(782, 2), 128>>>(gpaS, gpaD, gcaS, gcaD);
    // per-dst aggregation (2 GATs + SAGE mean)
    k_agg<<<dim3(N_NODES / 8, 3), 256>>>();
    // tensor-core SAGE GEMMs (W staged in smem) + combine
    k_final<<<782, 128>>>(gpB, gcB, sgB, out);
}

// round 16
// speedup vs baseline: 2.0601x; 1.0635x over previous
// R15: algebraic restructure — aggregate x then multiply by W (k_feat deleted; alpha via precomputed W@a vectors);
//      k_agg gathers one L2-resident array; k_final = 4 HMMA chains.
#include <cuda_runtime.h>
#include <cuda_fp16.h>
#include <math.h>

#define N_NODES 50000
#define DIM     128
#define N_EDGES 800000
#define NEG_SLOPE 0.2f
#define WSTRIDE 68        // padded W row stride (words): bank = 4n+kc, conflict-free

// ---------------- scratch (device globals) ------------------------------------
__device__ __half g_x16[N_NODES * DIM];       // fp16 x (gather source + A operand)
__device__ __half g_aggP16[N_NODES * DIM];    // GAT-parent weighted aggregate of x
__device__ __half g_aggC16[N_NODES * DIM];    // GAT-child weighted aggregate of x
__device__ __half g_accs16[N_NODES * DIM];    // SAGE mean of x
__device__ __half g_Wp16t[DIM * DIM];         // transposed fp16 weights [n][k]
__device__ __half g_Wc16t[DIM * DIM];
__device__ __half g_Wn16t[DIM * DIM];
__device__ __half g_Wr16t[DIM * DIM];
__device__ float g_va[4][DIM];                // W@a vectors: Wp@asP, Wp@adP, Wc@asC, Wc@adC
__device__ float g_asp[N_NODES], g_adp[N_NODES];
__device__ float g_asc[N_NODES], g_adc[N_NODES];
__device__ int g_cnt3[3][N_NODES];            // zeroed at load; re-zeroed by k_alloc each run
__device__ int g_rp3[3][N_NODES];             // segment start (not monotone across nodes)
__device__ int g_rpe3[3][N_NODES];            // segment end
__device__ int g_cur3[3][N_NODES];
__device__ int g_base3[3];                    // bump allocators; reset by k_count
__device__ int g_csrP[N_EDGES], g_csrC[N_EDGES], g_csrS[N_EDGES];

// ---------------- helpers -----------------------------------------------------
__device__ __forceinline__ float lrelu(float v) { return v > 0.f ? v : NEG_SLOPE * v; }

__device__ __forceinline__ float4 h2f4(uint2 v) {
    __half2 a = *reinterpret_cast<__half2*>(&v.x);
    __half2 b = *reinterpret_cast<__half2*>(&v.y);
    float2 fa = __half22float2(a), fb = __half22float2(b);
    return make_float4(fa.x, fa.y, fb.x, fb.y);
}

__device__ __forceinline__ void mma16816(float* c, const unsigned* a, unsigned b0, unsigned b1) {
    asm volatile(
        "mma.sync.aligned.m16n8k16.row.col.f32.f16.f16.f32 "
        "{%0,%1,%2,%3}, {%4,%5,%6,%7}, {%8,%9}, {%0,%1,%2,%3};"
        : "+f"(c[0]), "+f"(c[1]), "+f"(c[2]), "+f"(c[3])
        : "r"(a[0]), "r"(a[1]), "r"(a[2]), "r"(a[3]), "r"(b0), "r"(b1));
}

// ---------------- k_prepv: va = W @ a (4 vectors, one block) -------------------
__global__ void __launch_bounds__(512) k_prepv(
    const float* __restrict__ Wp, const float* __restrict__ Wc,
    const float* __restrict__ apS, const float* __restrict__ apD,
    const float* __restrict__ acS, const float* __restrict__ acD)
{
    int m = threadIdx.x >> 7, k = threadIdx.x & 127;
    const float* W = (m < 2) ? Wp : Wc;
    const float* a = (m == 0) ? apS : (m == 1) ? apD : (m == 2) ? acS : acD;
    float s0 = 0.f, s1 = 0.f, s2 = 0.f, s3 = 0.f;
#pragma unroll 8
    for (int j = 0; j < DIM; j += 4) {
        s0 = fmaf(W[k * DIM + j],     a[j],     s0);
        s1 = fmaf(W[k * DIM + j + 1], a[j + 1], s1);
        s2 = fmaf(W[k * DIM + j + 2], a[j + 2], s2);
        s3 = fmaf(W[k * DIM + j + 3], a[j + 3], s3);
    }
    g_va[m][k] = (s0 + s1) + (s2 + s3);
}

// ---------------- k_prepw: transposed fp16 weights -----------------------------
__global__ void __launch_bounds__(256) k_prepw(
    const float* __restrict__ Wp, const float* __restrict__ Wc,
    const float* __restrict__ Wn, const float* __restrict__ Wr)
{
    int m = blockIdx.y;
    const float* W = (m == 0) ? Wp : (m == 1) ? Wc : (m == 2) ? Wn : Wr;
    __half* Wt = (m == 0) ? g_Wp16t : (m == 1) ? g_Wc16t : (m == 2) ? g_Wn16t : g_Wr16t;
    int idx = blockIdx.x * 256 + threadIdx.x;
    int k = idx >> 7, n = idx & 127;
    Wt[n * DIM + k] = __float2half_rn(W[idx]);
}

// ---------------- k_prepx: x->fp16 + 4 alpha dots (warp per node) --------------
__global__ void __launch_bounds__(256) k_prepx(const float* __restrict__ x) {
    const int node = blockIdx.x * 8 + (threadIdx.x >> 5);
    const int lane = threadIdx.x & 31;
    float4 xv = *(const float4*)(x + (size_t)node * DIM + lane * 4);
    uint2 pk;
    *reinterpret_cast<__half2*>(&pk.x) = __floats2half2_rn(xv.x, xv.y);
    *reinterpret_cast<__half2*>(&pk.y) = __floats2half2_rn(xv.z, xv.w);
    ((uint2*)(g_x16 + (size_t)node * DIM))[lane] = pk;

    float4 v0 = *(const float4*)&g_va[0][lane * 4];
    float4 v1 = *(const float4*)&g_va[1][lane * 4];
    float4 v2 = *(const float4*)&g_va[2][lane * 4];
    float4 v3 = *(const float4*)&g_va[3][lane * 4];
    float d0 = xv.x * v0.x + xv.y * v0.y + xv.z * v0.z + xv.w * v0.w;
    float d1 = xv.x * v1.x + xv.y * v1.y + xv.z * v1.z + xv.w * v1.w;
    float d2 = xv.x * v2.x + xv.y * v2.y + xv.z * v2.z + xv.w * v2.w;
    float d3 = xv.x * v3.x + xv.y * v3.y + xv.z * v3.z + xv.w * v3.w;
#pragma unroll
    for (int o = 16; o; o >>= 1) {
        d0 += __shfl_xor_sync(0xffffffffu, d0, o);
        d1 += __shfl_xor_sync(0xffffffffu, d1, o);
        d2 += __shfl_xor_sync(0xffffffffu, d2, o);
        d3 += __shfl_xor_sync(0xffffffffu, d3, o);
    }
    if (lane == 0) {
        g_asp[node] = d0; g_adp[node] = d1;
        g_asc[node] = d2; g_adc[node] = d3;
    }
}

// ---------------- CSR build (count -> atomic segment alloc -> fill) ------------
__global__ void __launch_bounds__(256) k_count(
    const int* __restrict__ dP, const int* __restrict__ dC, const int* __restrict__ dS)
{
    int g = blockIdx.y;
    if (blockIdx.x == 0 && threadIdx.x == 0) g_base3[g] = 0;
    int e = blockIdx.x * 256 + threadIdx.x;
    const int* d = (g == 0) ? dP : (g == 1) ? dC : dS;
    atomicAdd(&g_cnt3[g][d[e]], 1);
}

__global__ void __launch_bounds__(256) k_alloc() {
    int g = blockIdx.y;
    int i = blockIdx.x * 256 + threadIdx.x;        // 196*256 = 50176 >= 50000
    int lane = threadIdx.x & 31;
    int deg = (i < N_NODES) ? g_cnt3[g][i] : 0;
    int s = deg;
#pragma unroll
    for (int o = 1; o < 32; o <<= 1) {
        int u = __shfl_up_sync(0xffffffffu, s, o);
        if (lane >= o) s += u;
    }
    int total = __shfl_sync(0xffffffffu, s, 31);
    int base0 = 0;
    if (lane == 0) base0 = atomicAdd(&g_base3[g], total);
    base0 = __shfl_sync(0xffffffffu, base0, 0);
    int mybase = base0 + s - deg;
    if (i < N_NODES) {
        g_rp3[g][i]  = mybase;
        g_rpe3[g][i] = mybase + deg;
        g_cur3[g][i] = mybase;
        g_cnt3[g][i] = 0;                          // restore invariant for graph replays
    }
}

__global__ void __launch_bounds__(256) k_fill(
    const int* __restrict__ sP, const int* __restrict__ dP,
    const int* __restrict__ sC, const int* __restrict__ dC,
    const int* __restrict__ sS, const int* __restrict__ dS)
{
    int g = blockIdx.y;
    int e = blockIdx.x * 256 + threadIdx.x;
    const int* src = (g == 0) ? sP : (g == 1) ? sC : sS;
    const int* dst = (g == 0) ? dP : (g == 1) ? dC : dS;
    int* csr       = (g == 0) ? g_csrP : (g == 1) ? g_csrC : g_csrS;
    int pos = atomicAdd(&g_cur3[g][dst[e]], 1);
    csr[pos] = src[e];
}

// ---------------- K_agg: gather x16 rows for all three relations ---------------
// blockIdx.y: 0 = GAT parent, 1 = GAT child, 2 = SAGE mean. Hot set = x16 only.
__global__ void __launch_bounds__(256) k_agg()
{
    const int which = blockIdx.y;
    const int node  = (blockIdx.x * 256 + threadIdx.x) >> 5;   // 6250*8 = 50000 exact
    const int lane  = threadIdx.x & 31;

    const int* csr = (which == 0) ? g_csrP : (which == 1) ? g_csrC : g_csrS;
    const int base = g_rp3[which][node], end = g_rpe3[which][node];
    float4 a;

    if (which < 2) {
        const float* as_ = which ? g_asc : g_asp;
        const float* ad_ = which ? g_adc : g_adp;
        const float ad_i = ad_[node];

        float den = __expf(lrelu(as_[node] + ad_i));   // self loop
        uint2 hvs = ((const uint2*)(g_x16 + (size_t)node * DIM))[lane];
        float4 fs = h2f4(hvs);
        a.x = den * fs.x; a.y = den * fs.y; a.z = den * fs.z; a.w = den * fs.w;

        for (int cs = base; cs < end; cs += 32) {
            int idx = cs + lane;
            bool vld = idx < end;
            int   s  = vld ? csr[idx] : 0;
            float ex = vld ? __expf(lrelu(as_[s] + ad_i)) : 0.f;
            float exs = ex;
#pragma unroll
            for (int o = 16; o; o >>= 1)
                exs += __shfl_xor_sync(0xffffffffu, exs, o);
            den += exs;
            const int n = min(32, end - cs);
#pragma unroll 8
            for (int t = 0; t < n; t++) {
                int   sb  = __shfl_sync(0xffffffffu, s,  t);
                float exb = __shfl_sync(0xffffffffu, ex, t);
                uint2 hv = ((const uint2*)(g_x16 + (size_t)sb * DIM))[lane];
                float4 f = h2f4(hv);
                a.x = fmaf(exb, f.x, a.x); a.y = fmaf(exb, f.y, a.y);
                a.z = fmaf(exb, f.z, a.z); a.w = fmaf(exb, f.w, a.w);
            }
        }
        float r = 1.f / den;
        a.x *= r; a.y *= r; a.z *= r; a.w *= r;
        __half* agg = which ? g_aggC16 : g_aggP16;
        uint2 pk;
        *reinterpret_cast<__half2*>(&pk.x) = __floats2half2_rn(a.x, a.y);
        *reinterpret_cast<__half2*>(&pk.y) = __floats2half2_rn(a.z, a.w);
        ((uint2*)(agg + (size_t)node * DIM))[lane] = pk;
    } else {
        a = make_float4(0.f, 0.f, 0.f, 0.f);
        for (int cs = base; cs < end; cs += 32) {
            int idx = cs + lane;
            int s   = (idx < end) ? csr[idx] : 0;
            const int n = min(32, end - cs);
#pragma unroll 8
            for (int t = 0; t < n; t++) {
                int sb = __shfl_sync(0xffffffffu, s, t);
                uint2 xv = ((const uint2*)(g_x16 + (size_t)sb * DIM))[lane];
                float4 f = h2f4(xv);
                a.x += f.x; a.y += f.y; a.z += f.z; a.w += f.w;
            }
        }
        float r = 1.f / fmaxf((float)(end - base), 1.f);
        uint2 pk;
        *reinterpret_cast<__half2*>(&pk.x) = __floats2half2_rn(a.x * r, a.y * r);
        *reinterpret_cast<__half2*>(&pk.y) = __floats2half2_rn(a.z * r, a.w * r);
        ((uint2*)(g_accs16 + (size_t)node * DIM))[lane] = pk;
    }
}

// ---------------- K_final: aggP·Wp + aggC·Wc + mean·Wn + x·Wr + biases ----------
// 4 warps/block, 16 rows each; 4 weight matrices staged sequentially in one buffer.
__global__ void __launch_bounds__(128) k_final(
    const float* __restrict__ bp, const float* __restrict__ bc,
    const float* __restrict__ bs, float* __restrict__ out)
{
    __shared__ unsigned sW[DIM * WSTRIDE];   // 34816 B, reused per chain
    const int w = threadIdx.x >> 5, lane = threadIdx.x & 31;
    const int rA  = blockIdx.x * 64 + w * 16 + (lane >> 2);
    const int rA0 = min(rA, N_NODES - 1);
    const int rA1 = min(rA + 8, N_NODES - 1);
    const int kc  = (lane & 3) * 2;
    const int bq  = lane & 3;

    float acc[16][4];
#pragma unroll
    for (int nt = 0; nt < 16; nt++) { acc[nt][0] = acc[nt][1] = acc[nt][2] = acc[nt][3] = 0.f; }

#pragma unroll
    for (int chain = 0; chain < 4; chain++) {
        const __half* Wt = (chain == 0) ? g_Wp16t : (chain == 1) ? g_Wc16t
                         : (chain == 2) ? g_Wn16t : g_Wr16t;
        const __half* A  = (chain == 0) ? g_aggP16 : (chain == 1) ? g_aggC16
                         : (chain == 2) ? g_accs16 : g_x16;
        if (chain) __syncthreads();          // drain previous chain's LDS before restage
        for (int i = threadIdx.x; i < DIM * 16; i += 128) {
            int row = i >> 4, c = i & 15;
            uint4 v = ((const uint4*)(Wt + row * DIM))[c];
            *(uint4*)&sW[row * WSTRIDE + c * 4] = v;
        }
        __syncthreads();
#pragma unroll 2
        for (int ks = 0; ks < 8; ks++) {
            const int k0 = ks * 16;
            unsigned a[4];
            a[0] = *(const unsigned*)(A + (size_t)rA0 * DIM + k0 + kc);
            a[1] = *(const unsigned*)(A + (size_t)rA1 * DIM + k0 + kc);
            a[2] = *(const unsigned*)(A + (size_t)rA0 * DIM + k0 + kc + 8);
            a[3] = *(const unsigned*)(A + (size_t)rA1 * DIM + k0 + kc + 8);
            const int kw = ks * 8 + bq;
#pragma unroll
            for (int nt = 0; nt < 16; nt++) {
                const unsigned* wrow = &sW[(nt * 8 + (lane >> 2)) * WSTRIDE + kw];
                mma16816(acc[nt], a, wrow[0], wrow[4]);
            }
        }
    }

    const bool ok0 = rA < N_NODES, ok1 = (rA + 8) < N_NODES;
#pragma unroll
    for (int nt = 0; nt < 16; nt++) {
        const int c0 = nt * 8 + (lane & 3) * 2;
        float b0 = bp[c0] + bc[c0] + bs[c0];
        float b1 = bp[c0 + 1] + bc[c0 + 1] + bs[c0 + 1];
        if (ok0) {
            float2 o;
            o.x = (acc[nt][0] + b0) * (1.f / 3.f);
            o.y = (acc[nt][1] + b1) * (1.f / 3.f);
            *(float2*)(out + (size_t)rA * DIM + c0) = o;
        }
        if (ok1) {
            float2 o;
            o.x = (acc[nt][2] + b0) * (1.f / 3.f);
            o.y = (acc[nt][3] + b1) * (1.f / 3.f);
            *(float2*)(out + (size_t)(rA + 8) * DIM + c0) = o;
        }
    }
}

// ---------------- launch ------------------------------------------------------
extern "C" void kernel_launch(void* const* d_in, const int* in_sizes, int n_in,
                              void* d_out, int out_size)
{
    const float* x    = (const float*)d_in[0];
    const int*   eip  = (const int*)d_in[1];   // [2, E]: src then dst
    const int*   eic  = (const int*)d_in[2];
    const int*   eir  = (const int*)d_in[3];
    const float* gpW  = (const float*)d_in[4];
    const float* gpaS = (const float*)d_in[5];
    const float* gpaD = (const float*)d_in[6];
    const float* gpB  = (const float*)d_in[7];
    const float* gcW  = (const float*)d_in[8];
    const float* gcaS = (const float*)d_in[9];
    const float* gcaD = (const float*)d_in[10];
    const float* gcB  = (const float*)d_in[11];
    const float* sgWn = (const float*)d_in[12];
    const float* sgWr = (const float*)d_in[13];
    const float* sgB  = (const float*)d_in[14];
    float* out = (float*)d_out;

    // CSR: count(1) -> alloc(2); prepv(3); fill(4 — ncu slot); prepw(5); prepx(6)
    k_count<<<dim3(N_EDGES / 256, 3), 256>>>(eip + N_EDGES, eic + N_EDGES, eir + N_EDGES);
    k_alloc<<<dim3(196, 3), 256>>>();
    k_prepv<<<1, 512>>>(gpW, gcW, gpaS, gpaD, gcaS, gcaD);
    k_fill<<<dim3(N_EDGES / 256, 3), 256>>>(eip, eip + N_EDGES,
                                            eic, eic + N_EDGES,
                                            eir, eir + N_EDGES);
    k_prepw<<<dim3(64, 4), 256>>>(gpW, gcW, sgWn, sgWr);
    k_prepx<<<6250, 256>>>(x);
    // per-dst aggregation of x rows (2 GATs + SAGE mean)
    k_agg<<<dim3(N_NODES / 8, 3), 256>>>();
    // fused 4-chain tensor-core GEMM + combine
    k_final<<<782, 128>>>(gpB, gcB, sgB, out);
}

// round 17
// speedup vs baseline: 2.1163x; 1.0273x over previous
// R16: paired-edge uint4 gather in k_agg (2 edges/iter, 2x MLP); kernel fusion -> k_agg in ncu slot #4.
#include <cuda_runtime.h>
#include <cuda_fp16.h>
#include <math.h>

#define N_NODES 50000
#define DIM     128
#define N_EDGES 800000
#define NEG_SLOPE 0.2f
#define WSTRIDE 68        // padded W row stride (words): bank-conflict-free fragment loads

// ---------------- scratch (device globals) ------------------------------------
__device__ __half g_x16[N_NODES * DIM];       // fp16 x (gather source + A operand)
__device__ __half g_aggP16[N_NODES * DIM];    // GAT-parent weighted aggregate of x
__device__ __half g_aggC16[N_NODES * DIM];    // GAT-child weighted aggregate of x
__device__ __half g_accs16[N_NODES * DIM];    // SAGE mean of x
__device__ __half g_Wp16t[DIM * DIM];         // transposed fp16 weights [n][k]
__device__ __half g_Wc16t[DIM * DIM];
__device__ __half g_Wn16t[DIM * DIM];
__device__ __half g_Wr16t[DIM * DIM];
__device__ float g_va[4][DIM];                // W@a: Wp@asP, Wp@adP, Wc@asC, Wc@adC
__device__ float g_asp[N_NODES], g_adp[N_NODES];
__device__ float g_asc[N_NODES], g_adc[N_NODES];
__device__ int g_cnt3[3][N_NODES];            // zeroed at load; re-zeroed by k_alloc each run
__device__ int g_rp3[3][N_NODES];
__device__ int g_rpe3[3][N_NODES];
__device__ int g_cur3[3][N_NODES];
__device__ int g_base3[3];                    // bump allocators; reset by k_pre
__device__ int g_csrP[N_EDGES], g_csrC[N_EDGES], g_csrS[N_EDGES];

// ---------------- helpers -----------------------------------------------------
__device__ __forceinline__ float lrelu(float v) { return v > 0.f ? v : NEG_SLOPE * v; }

__device__ __forceinline__ float4 h2f4(unsigned lo, unsigned hi) {
    __half2 a = *reinterpret_cast<__half2*>(&lo);
    __half2 b = *reinterpret_cast<__half2*>(&hi);
    float2 fa = __half22float2(a), fb = __half22float2(b);
    return make_float4(fa.x, fa.y, fb.x, fb.y);
}

__device__ __forceinline__ void mma16816(float* c, const unsigned* a, unsigned b0, unsigned b1) {
    asm volatile(
        "mma.sync.aligned.m16n8k16.row.col.f32.f16.f16.f32 "
        "{%0,%1,%2,%3}, {%4,%5,%6,%7}, {%8,%9}, {%0,%1,%2,%3};"
        : "+f"(c[0]), "+f"(c[1]), "+f"(c[2]), "+f"(c[3])
        : "r"(a[0]), "r"(a[1]), "r"(a[2]), "r"(a[3]), "r"(b0), "r"(b1));
}

// ---------------- k_pre: fused count + prepv + prepw ---------------------------
// blocks [0, 9375): edge count. [9375, 9377): va=W@a. [9377, 9633): Wt fp16.
__global__ void __launch_bounds__(256) k_pre(
    const int* __restrict__ dP, const int* __restrict__ dC, const int* __restrict__ dS,
    const float* __restrict__ Wp, const float* __restrict__ Wc,
    const float* __restrict__ Wn, const float* __restrict__ Wr,
    const float* __restrict__ apS, const float* __restrict__ apD,
    const float* __restrict__ acS, const float* __restrict__ acD)
{
    const int blk = blockIdx.x, tid = threadIdx.x;
    if (blk < 9375) {
        if (blk == 0 && tid < 3) g_base3[tid] = 0;
        int g = blk / 3125;
        int e = (blk % 3125) * 256 + tid;
        const int* d = (g == 0) ? dP : (g == 1) ? dC : dS;
        atomicAdd(&g_cnt3[g][d[e]], 1);
    } else if (blk < 9377) {
        int m = (blk - 9375) * 2 + (tid >> 7);
        int k = tid & 127;
        const float* W = (m < 2) ? Wp : Wc;
        const float* a = (m == 0) ? apS : (m == 1) ? apD : (m == 2) ? acS : acD;
        float s0 = 0.f, s1 = 0.f, s2 = 0.f, s3 = 0.f;
#pragma unroll 8
        for (int j = 0; j < DIM; j += 4) {
            s0 = fmaf(W[k * DIM + j],     a[j],     s0);
            s1 = fmaf(W[k * DIM + j + 1], a[j + 1], s1);
            s2 = fmaf(W[k * DIM + j + 2], a[j + 2], s2);
            s3 = fmaf(W[k * DIM + j + 3], a[j + 3], s3);
        }
        g_va[m][k] = (s0 + s1) + (s2 + s3);
    } else {
        int b = blk - 9377;
        int m = b >> 6;
        int idx = (b & 63) * 256 + tid;
        const float* W = (m == 0) ? Wp : (m == 1) ? Wc : (m == 2) ? Wn : Wr;
        __half* Wt = (m == 0) ? g_Wp16t : (m == 1) ? g_Wc16t : (m == 2) ? g_Wn16t : g_Wr16t;
        int k = idx >> 7, n = idx & 127;
        Wt[n * DIM + k] = __float2half_rn(W[idx]);
    }
}

// ---------------- k_alloc: warp-aggregated atomic segment alloc ----------------
__global__ void __launch_bounds__(256) k_alloc() {
    int g = blockIdx.y;
    int i = blockIdx.x * 256 + threadIdx.x;        // 196*256 = 50176 >= 50000
    int lane = threadIdx.x & 31;
    int deg = (i < N_NODES) ? g_cnt3[g][i] : 0;
    int s = deg;
#pragma unroll
    for (int o = 1; o < 32; o <<= 1) {
        int u = __shfl_up_sync(0xffffffffu, s, o);
        if (lane >= o) s += u;
    }
    int total = __shfl_sync(0xffffffffu, s, 31);
    int base0 = 0;
    if (lane == 0) base0 = atomicAdd(&g_base3[g], total);
    base0 = __shfl_sync(0xffffffffu, base0, 0);
    int mybase = base0 + s - deg;
    if (i < N_NODES) {
        g_rp3[g][i]  = mybase;
        g_rpe3[g][i] = mybase + deg;
        g_cur3[g][i] = mybase;
        g_cnt3[g][i] = 0;                          // restore invariant for graph replays
    }
}

// ---------------- k_fill2: fused CSR fill + prepx (x->fp16 + alpha dots) -------
// blocks [0, 9375): fill. [9375, 15625): prepx (reads g_va from k_pre — prior launch).
__global__ void __launch_bounds__(256) k_fill2(
    const int* __restrict__ sP, const int* __restrict__ dP,
    const int* __restrict__ sC, const int* __restrict__ dC,
    const int* __restrict__ sS, const int* __restrict__ dS,
    const float* __restrict__ x)
{
    const int blk = blockIdx.x, tid = threadIdx.x;
    if (blk < 9375) {
        int g = blk / 3125;
        int e = (blk % 3125) * 256 + tid;
        const int* src = (g == 0) ? sP : (g == 1) ? sC : sS;
        const int* dst = (g == 0) ? dP : (g == 1) ? dC : dS;
        int* csr       = (g == 0) ? g_csrP : (g == 1) ? g_csrC : g_csrS;
        int pos = atomicAdd(&g_cur3[g][dst[e]], 1);
        csr[pos] = src[e];
    } else {
        const int node = (blk - 9375) * 8 + (tid >> 5);
        const int lane = tid & 31;
        float4 xv = *(const float4*)(x + (size_t)node * DIM + lane * 4);
        uint2 pk;
        *reinterpret_cast<__half2*>(&pk.x) = __floats2half2_rn(xv.x, xv.y);
        *reinterpret_cast<__half2*>(&pk.y) = __floats2half2_rn(xv.z, xv.w);
        ((uint2*)(g_x16 + (size_t)node * DIM))[lane] = pk;

        float4 v0 = *(const float4*)&g_va[0][lane * 4];
        float4 v1 = *(const float4*)&g_va[1][lane * 4];
        float4 v2 = *(const float4*)&g_va[2][lane * 4];
        float4 v3 = *(const float4*)&g_va[3][lane * 4];
        float d0 = xv.x * v0.x + xv.y * v0.y + xv.z * v0.z + xv.w * v0.w;
        float d1 = xv.x * v1.x + xv.y * v1.y + xv.z * v1.z + xv.w * v1.w;
        float d2 = xv.x * v2.x + xv.y * v2.y + xv.z * v2.z + xv.w * v2.w;
        float d3 = xv.x * v3.x + xv.y * v3.y + xv.z * v3.z + xv.w * v3.w;
#pragma unroll
        for (int o = 16; o; o >>= 1) {
            d0 += __shfl_xor_sync(0xffffffffu, d0, o);
            d1 += __shfl_xor_sync(0xffffffffu, d1, o);
            d2 += __shfl_xor_sync(0xffffffffu, d2, o);
            d3 += __shfl_xor_sync(0xffffffffu, d3, o);
        }
        if (lane == 0) {
            g_asp[node] = d0; g_adp[node] = d1;
            g_asc[node] = d2; g_adc[node] = d3;
        }
    }
}

// ---------------- K_agg: paired-edge uint4 gather (2 edges/iter) ---------------
// Lanes 0-15 cover edge t's 256B row (16B/lane); lanes 16-31 cover edge t+1.
__global__ void __launch_bounds__(256) k_agg()
{
    const int which = blockIdx.y;
    const int node  = (blockIdx.x * 256 + threadIdx.x) >> 5;   // 6250*8 = 50000 exact
    const int lane  = threadIdx.x & 31;
    const int half  = lane >> 4;
    const int sub   = lane & 15;

    const int* csr = (which == 0) ? g_csrP : (which == 1) ? g_csrC : g_csrS;
    const int base = g_rp3[which][node], end = g_rpe3[which][node];

    float acc[8];
#pragma unroll
    for (int i = 0; i < 8; i++) acc[i] = 0.f;

    if (which < 2) {
        const float* as_ = which ? g_asc : g_asp;
        const float* ad_ = which ? g_adc : g_adp;
        const float ad_i = ad_[node];

        float den = __expf(lrelu(as_[node] + ad_i));   // self loop
        if (half == 0) {
            uint4 hv = ((const uint4*)(g_x16 + (size_t)node * DIM))[sub];
            float4 f01 = h2f4(hv.x, hv.y), f23 = h2f4(hv.z, hv.w);
            acc[0] = den * f01.x; acc[1] = den * f01.y;
            acc[2] = den * f01.z; acc[3] = den * f01.w;
            acc[4] = den * f23.x; acc[5] = den * f23.y;
            acc[6] = den * f23.z; acc[7] = den * f23.w;
        }

        for (int cs = base; cs < end; cs += 32) {
            int idx = cs + lane;
            bool vld = idx < end;
            int   s  = vld ? csr[idx] : 0;
            float ex = vld ? __expf(lrelu(as_[s] + ad_i)) : 0.f;
            float exs = ex;
#pragma unroll
            for (int o = 16; o; o >>= 1)
                exs += __shfl_xor_sync(0xffffffffu, exs, o);
            den += exs;
            const int n = min(32, end - cs);
#pragma unroll 8
            for (int t = 0; t < n; t += 2) {
                int tt = t + half;
                int   sb  = __shfl_sync(0xffffffffu, s,  tt & 31);
                float exb = __shfl_sync(0xffffffffu, ex, tt & 31);
                if (tt >= n) exb = 0.f;
                uint4 hv = ((const uint4*)(g_x16 + (size_t)sb * DIM))[sub];
                float4 f01 = h2f4(hv.x, hv.y), f23 = h2f4(hv.z, hv.w);
                acc[0] = fmaf(exb, f01.x, acc[0]); acc[1] = fmaf(exb, f01.y, acc[1]);
                acc[2] = fmaf(exb, f01.z, acc[2]); acc[3] = fmaf(exb, f01.w, acc[3]);
                acc[4] = fmaf(exb, f23.x, acc[4]); acc[5] = fmaf(exb, f23.y, acc[5]);
                acc[6] = fmaf(exb, f23.z, acc[6]); acc[7] = fmaf(exb, f23.w, acc[7]);
            }
        }
        float r = 1.f / den;
#pragma unroll
        for (int i = 0; i < 8; i++) {
            acc[i] += __shfl_xor_sync(0xffffffffu, acc[i], 16);
            acc[i] *= r;
        }
        if (half == 0) {
            __half* agg = which ? g_aggC16 : g_aggP16;
            uint4 pk;
            *reinterpret_cast<__half2*>(&pk.x) = __floats2half2_rn(acc[0], acc[1]);
            *reinterpret_cast<__half2*>(&pk.y) = __floats2half2_rn(acc[2], acc[3]);
            *reinterpret_cast<__half2*>(&pk.z) = __floats2half2_rn(acc[4], acc[5]);
            *reinterpret_cast<__half2*>(&pk.w) = __floats2half2_rn(acc[6], acc[7]);
            ((uint4*)(agg + (size_t)node * DIM))[sub] = pk;
        }
    } else {
        for (int cs = base; cs < end; cs += 32) {
            int idx = cs + lane;
            int s   = (idx < end) ? csr[idx] : 0;
            const int n = min(32, end - cs);
#pragma unroll 8
            for (int t = 0; t < n; t += 2) {
                int tt = t + half;
                int sb = __shfl_sync(0xffffffffu, s, tt & 31);
                float m = (tt < n) ? 1.f : 0.f;
                uint4 xv = ((const uint4*)(g_x16 + (size_t)sb * DIM))[sub];
                float4 f01 = h2f4(xv.x, xv.y), f23 = h2f4(xv.z, xv.w);
                acc[0] = fmaf(m, f01.x, acc[0]); acc[1] = fmaf(m, f01.y, acc[1]);
                acc[2] = fmaf(m, f01.z, acc[2]); acc[3] = fmaf(m, f01.w, acc[3]);
                acc[4] = fmaf(m, f23.x, acc[4]); acc[5] = fmaf(m, f23.y, acc[5]);
                acc[6] = fmaf(m, f23.z, acc[6]); acc[7] = fmaf(m, f23.w, acc[7]);
            }
        }
        float r = 1.f / fmaxf((float)(end - base), 1.f);
#pragma unroll
        for (int i = 0; i < 8; i++) {
            acc[i] += __shfl_xor_sync(0xffffffffu, acc[i], 16);
            acc[i] *= r;
        }
        if (half == 0) {
            uint4 pk;
            *reinterpret_cast<__half2*>(&pk.x) = __floats2half2_rn(acc[0], acc[1]);
            *reinterpret_cast<__half2*>(&pk.y) = __floats2half2_rn(acc[2], acc[3]);
            *reinterpret_cast<__half2*>(&pk.z) = __floats2half2_rn(acc[4], acc[5]);
            *reinterpret_cast<__half2*>(&pk.w) = __floats2half2_rn(acc[6], acc[7]);
            ((uint4*)(g_accs16 + (size_t)node * DIM))[sub] = pk;
        }
    }
}

// ---------------- K_final: aggP·Wp + aggC·Wc + mean·Wn + x·Wr + biases ----------
__global__ void __launch_bounds__(128) k_final(
    const float* __restrict__ bp, const float* __restrict__ bc,
    const float* __restrict__ bs, float* __restrict__ out)
{
    __shared__ unsigned sW[DIM * WSTRIDE];   // 34816 B, reused per chain
    const int w = threadIdx.x >> 5, lane = threadIdx.x & 31;
    const int rA  = blockIdx.x * 64 + w * 16 + (lane >> 2);
    const int rA0 = min(rA, N_NODES - 1);
    const int rA1 = min(rA + 8, N_NODES - 1);
    const int kc  = (lane & 3) * 2;
    const int bq  = lane & 3;

    float acc[16][4];
#pragma unroll
    for (int nt = 0; nt < 16; nt++) { acc[nt][0] = acc[nt][1] = acc[nt][2] = acc[nt][3] = 0.f; }

#pragma unroll
    for (int chain = 0; chain < 4; chain++) {
        const __half* Wt = (chain == 0) ? g_Wp16t : (chain == 1) ? g_Wc16t
                         : (chain == 2) ? g_Wn16t : g_Wr16t;
        const __half* A  = (chain == 0) ? g_aggP16 : (chain == 1) ? g_aggC16
                         : (chain == 2) ? g_accs16 : g_x16;
        if (chain) __syncthreads();
        for (int i = threadIdx.x; i < DIM * 16; i += 128) {
            int row = i >> 4, c = i & 15;
            uint4 v = ((const uint4*)(Wt + row * DIM))[c];
            *(uint4*)&sW[row * WSTRIDE + c * 4] = v;
        }
        __syncthreads();
#pragma unroll 2
        for (int ks = 0; ks < 8; ks++) {
            const int k0 = ks * 16;
            unsigned a[4];
            a[0] = *(const unsigned*)(A + (size_t)rA0 * DIM + k0 + kc);
            a[1] = *(const unsigned*)(A + (size_t)rA1 * DIM + k0 + kc);
            a[2] = *(const unsigned*)(A + (size_t)rA0 * DIM + k0 + kc + 8);
            a[3] = *(const unsigned*)(A + (size_t)rA1 * DIM + k0 + kc + 8);
            const int kw = ks * 8 + bq;
#pragma unroll
            for (int nt = 0; nt < 16; nt++) {
                const unsigned* wrow = &sW[(nt * 8 + (lane >> 2)) * WSTRIDE + kw];
                mma16816(acc[nt], a, wrow[0], wrow[4]);
            }
        }
    }

    const bool ok0 = rA < N_NODES, ok1 = (rA + 8) < N_NODES;
#pragma unroll
    for (int nt = 0; nt < 16; nt++) {
        const int c0 = nt * 8 + (lane & 3) * 2;
        float b0 = bp[c0] + bc[c0] + bs[c0];
        float b1 = bp[c0 + 1] + bc[c0 + 1] + bs[c0 + 1];
        if (ok0) {
            float2 o;
            o.x = (acc[nt][0] + b0) * (1.f / 3.f);
            o.y = (acc[nt][1] + b1) * (1.f / 3.f);
            *(float2*)(out + (size_t)rA * DIM + c0) = o;
        }
        if (ok1) {
            float2 o;
            o.x = (acc[nt][2] + b0) * (1.f / 3.f);
            o.y = (acc[nt][3] + b1) * (1.f / 3.f);
            *(float2*)(out + (size_t)(rA + 8) * DIM + c0) = o;
        }
    }
}

// ---------------- launch ------------------------------------------------------
extern "C" void kernel_launch(void* const* d_in, const int* in_sizes, int n_in,
                              void* d_out, int out_size)
{
    const float* x    = (const float*)d_in[0];
    const int*   eip  = (const int*)d_in[1];   // [2, E]: src then dst
    const int*   eic  = (const int*)d_in[2];
    const int*   eir  = (const int*)d_in[3];
    const float* gpW  = (const float*)d_in[4];
    const float* gpaS = (const float*)d_in[5];
    const float* gpaD = (const float*)d_in[6];
    const float* gpB  = (const float*)d_in[7];
    const float* gcW  = (const float*)d_in[8];
    const float* gcaS = (const float*)d_in[9];
    const float* gcaD = (const float*)d_in[10];
    const float* gcB  = (const float*)d_in[11];
    const float* sgWn = (const float*)d_in[12];
    const float* sgWr = (const float*)d_in[13];
    const float* sgB  = (const float*)d_in[14];
    float* out = (float*)d_out;

    // 1: fused count + W@a vectors + fp16 weights
    k_pre<<<9633, 256>>>(eip + N_EDGES, eic + N_EDGES, eir + N_EDGES,
                         gpW, gcW, sgWn, sgWr, gpaS, gpaD, gcaS, gcaD);
    // 2: segment alloc
    k_alloc<<<dim3(196, 3), 256>>>();
    // 3: fused CSR fill + x->fp16 + alpha dots
    k_fill2<<<15625, 256>>>(eip, eip + N_EDGES, eic, eic + N_EDGES,
                            eir, eir + N_EDGES, x);
    // 4: paired-edge aggregation (ncu slot)
    k_agg<<<dim3(N_NODES / 8, 3), 256>>>();
    // 5: fused 4-chain tensor-core GEMM + combine
    k_final<<<782, 128>>>(gpB, gcB, sgB, out);
}